// round 15
// baseline (speedup 1.0000x reference)
#include <cuda_runtime.h>
#include <math.h>
#include <stdint.h>

// Problem constants
#define TOK   4096   // B*L = 2*2048
#define DIMK  1024
#define HQ    16
#define HKV   4
#define HD    64
#define LSEQ  2048

// Scratch (static device globals — allocation-free)
__device__ float g_q [TOK * HQ  * HD];   // [token][h*64+d]  (normed * 1/8)
__device__ float g_k [TOK * HKV * HD];   // [token][kv*64+d] (normed)
__device__ float g_v [TOK * HKV * HD];
__device__ float g_ao[TOK * HQ  * HD];   // attention out, tf32-rounded on store

// tf32-pre-rounded operands (so GEMM staging is a raw cp.async copy)
__device__ float g_xr [TOK * DIMK];          // rounded x
__device__ float g_wqr[HQ  * HD * DIMK];     // rounded wq
__device__ float g_wkr[HKV * HD * DIMK];     // rounded wk
__device__ float g_wvr[HKV * HD * DIMK];     // rounded wv
__device__ float g_wor[DIMK * HQ * HD];      // rounded wo

// ---------------------------------------------------------------------------
// tf32 helpers
// ---------------------------------------------------------------------------
__device__ __forceinline__ unsigned f2tf(float f) {
    unsigned r;
    asm("cvt.rna.tf32.f32 %0, %1;" : "=r"(r) : "f"(f));
    return r;
}

__device__ __forceinline__ void mma_tf32(float& c0, float& c1, float& c2, float& c3,
                                         unsigned a0, unsigned a1, unsigned a2, unsigned a3,
                                         unsigned b0, unsigned b1)
{
    asm volatile(
        "mma.sync.aligned.m16n8k8.row.col.f32.tf32.tf32.f32 "
        "{%0,%1,%2,%3}, {%4,%5,%6,%7}, {%8,%9}, {%0,%1,%2,%3};"
        : "+f"(c0), "+f"(c1), "+f"(c2), "+f"(c3)
        : "r"(a0), "r"(a1), "r"(a2), "r"(a3), "r"(b0), "r"(b1));
}

__device__ __forceinline__ uint32_t smem_u32(const void* p) {
    uint32_t a;
    asm("{ .reg .u64 t; cvta.to.shared.u64 t, %1; cvt.u32.u64 %0, t; }" : "=r"(a) : "l"(p));
    return a;
}

__device__ __forceinline__ void cp16(uint32_t dst, const void* src) {
    asm volatile("cp.async.cg.shared.global [%0], [%1], 16;" :: "r"(dst), "l"(src));
}
__device__ __forceinline__ void cp_commit() {
    asm volatile("cp.async.commit_group;" ::: "memory");
}
template <int N>
__device__ __forceinline__ void cp_wait() {
    asm volatile("cp.async.wait_group %0;" :: "n"(N) : "memory");
}

// ---------------------------------------------------------------------------
// Pre-rounding pass: fp32 -> tf32-rounded fp32, elementwise.
// Blocks 0..1023 -> x, 1024..1279 -> wq, 1280..1343 -> wk,
// 1344..1407 -> wv, 1408..1663 -> wo. 4096 elems/block.
// ---------------------------------------------------------------------------
__global__ void round_kernel(const float* __restrict__ x,  const float* __restrict__ wq,
                             const float* __restrict__ wk, const float* __restrict__ wv,
                             const float* __restrict__ wo)
{
    const int b = blockIdx.x;
    const float* src;
    float* dst;
    int base;
    if      (b < 1024) { src = x;  dst = g_xr;  base = b; }
    else if (b < 1280) { src = wq; dst = g_wqr; base = b - 1024; }
    else if (b < 1344) { src = wk; dst = g_wkr; base = b - 1280; }
    else if (b < 1408) { src = wv; dst = g_wvr; base = b - 1344; }
    else               { src = wo; dst = g_wor; base = b - 1408; }
    size_t off = (size_t)base * 4096 + threadIdx.x * 4;
#pragma unroll
    for (int i = 0; i < 4; i++) {
        float4 v = *(const float4*)(src + off + i * 1024);
        uint4 r = make_uint4(f2tf(v.x), f2tf(v.y), f2tf(v.z), f2tf(v.w));
        *(uint4*)(dst + off + i * 1024) = r;
    }
}

// ---------------------------------------------------------------------------
// 128x128 tile GEMM, tensor cores (tf32), C[m,n] = sum_k A[m,k]*B[n,k].
// Operands are PRE-ROUNDED to tf32 -> staging is raw cp.async 16B copies.
// BK=32, 3-stage cp.async ring (prefetch depth 2), 256 threads, 8 warps
// (4x2), each warp 32x64 via 2x8 m16n8k8. Fused per-head RMSNorm epilogue.
// ---------------------------------------------------------------------------
#define SROW 36                         // padded row stride (words)
#define STG_WORDS  (128 * SROW)         // one operand, one stage
#define STG_BYTES  (STG_WORDS * 4)      // 18432
#define STAGE_WORDS (2 * STG_WORDS)     // A+B per stage
#define STAGE_BYTES (STAGE_WORDS * 4)   // 36864
#define NSTAGE 3
#define DSMEM_SZ (NSTAGE * STAGE_BYTES) // 110592
#define NSLAB (DIMK / 32)               // 32

__device__ __forceinline__ void gemm128_tc(const float* __restrict__ Ag,
                                           const float* __restrict__ Bg,
                                           float*       __restrict__ Cg,
                                           int ldc,
                                           const float* __restrict__ nw,  // null = plain store
                                           float outScale)
{
    extern __shared__ unsigned sh[];   // [NSTAGE][A|B][128*SROW]

    const int tid    = threadIdx.x;
    const int lane   = tid & 31;
    const int wid    = tid >> 5;
    const int warp_m = (wid & 3) * 32;
    const int warp_n = (wid >> 2) * 64;
    const int g      = lane >> 2;
    const int tig    = lane & 3;

    float acc[2][8][4];
#pragma unroll
    for (int mt = 0; mt < 2; mt++)
#pragma unroll
        for (int nt = 0; nt < 8; nt++)
#pragma unroll
            for (int c = 0; c < 4; c++) acc[mt][nt][c] = 0.0f;

    // Staging: thread owns 16 consecutive floats of one row per operand.
    const int srow = tid >> 1;
    const int sc0  = (tid & 1) * 16;
    const float* Ap = Ag + (size_t)srow * DIMK + sc0;
    const float* Bp = Bg + (size_t)srow * DIMK + sc0;
    const uint32_t sbase = smem_u32(sh);
    const uint32_t soff  = (srow * SROW + sc0) * 4;   // byte offset in operand buf

    // issue slab s into stage s%NSTAGE (8 x cp.async.cg 16B), one commit group
#define ISSUE_SLAB(s)                                                          \
    do {                                                                       \
        const uint32_t stb = sbase + ((s) % NSTAGE) * STAGE_BYTES;             \
        const float* a_ = Ap + (s) * 32;                                       \
        const float* b_ = Bp + (s) * 32;                                       \
        _Pragma("unroll")                                                      \
        for (int i_ = 0; i_ < 4; i_++) {                                       \
            cp16(stb + soff + i_ * 16,             a_ + i_ * 4);               \
            cp16(stb + STG_BYTES + soff + i_ * 16, b_ + i_ * 4);               \
        }                                                                      \
        cp_commit();                                                           \
    } while (0)

    ISSUE_SLAB(0);
    ISSUE_SLAB(1);

    for (int s = 0; s < NSLAB; s++) {
        cp_wait<1>();        // group for slab s complete (in-order completion)
        __syncthreads();     // data visible; all warps done with slab s-1

        if (s + 2 < NSLAB) ISSUE_SLAB(s + 2);   // writes stage (s+2)%3 = (s-1)%3: safe

        const unsigned* Ac = sh + (s % NSTAGE) * STAGE_WORDS;
        const unsigned* Bc = Ac + STG_WORDS;

#pragma unroll
        for (int ks = 0; ks < 4; ks++) {
            const int kk = ks * 8;
            unsigned a[2][4];
#pragma unroll
            for (int mt = 0; mt < 2; mt++) {
                const int mr = warp_m + mt * 16 + g;
                a[mt][0] = Ac[mr * SROW + kk + tig];
                a[mt][1] = Ac[(mr + 8) * SROW + kk + tig];
                a[mt][2] = Ac[mr * SROW + kk + tig + 4];
                a[mt][3] = Ac[(mr + 8) * SROW + kk + tig + 4];
            }
#pragma unroll
            for (int nt = 0; nt < 8; nt++) {
                const int nr = warp_n + nt * 8 + g;
                const unsigned b0 = Bc[nr * SROW + kk + tig];
                const unsigned b1 = Bc[nr * SROW + kk + tig + 4];
                mma_tf32(acc[0][nt][0], acc[0][nt][1], acc[0][nt][2], acc[0][nt][3],
                         a[0][0], a[0][1], a[0][2], a[0][3], b0, b1);
                mma_tf32(acc[1][nt][0], acc[1][nt][1], acc[1][nt][2], acc[1][nt][3],
                         a[1][0], a[1][1], a[1][2], a[1][3], b0, b1);
            }
        }
        __syncthreads();     // all warps done reading stage s before overwrite
    }
#undef ISSUE_SLAB

    // ---------------- Epilogue ----------------
    if (nw == nullptr) {
#pragma unroll
        for (int mt = 0; mt < 2; mt++)
#pragma unroll
            for (int nt = 0; nt < 8; nt++) {
                const int r0 = warp_m + mt * 16 + g;
                const int c  = warp_n + nt * 8 + tig * 2;
                *(float2*)(Cg + (size_t)r0 * ldc + c)       = make_float2(acc[mt][nt][0], acc[mt][nt][1]);
                *(float2*)(Cg + (size_t)(r0 + 8) * ldc + c) = make_float2(acc[mt][nt][2], acc[mt][nt][3]);
            }
    } else {
        // Fused per-head RMSNorm: warp's 64-col span is one 64-dim head.
        float w[16];
#pragma unroll
        for (int nt = 0; nt < 8; nt++) {
            float2 ww = *(const float2*)(nw + nt * 8 + tig * 2);
            w[nt * 2]     = ww.x;
            w[nt * 2 + 1] = ww.y;
        }
#pragma unroll
        for (int mt = 0; mt < 2; mt++) {
            float s0 = 0.f, s1 = 0.f;
#pragma unroll
            for (int nt = 0; nt < 8; nt++) {
                s0 += acc[mt][nt][0] * acc[mt][nt][0] + acc[mt][nt][1] * acc[mt][nt][1];
                s1 += acc[mt][nt][2] * acc[mt][nt][2] + acc[mt][nt][3] * acc[mt][nt][3];
            }
            s0 += __shfl_xor_sync(0xffffffffu, s0, 1);
            s0 += __shfl_xor_sync(0xffffffffu, s0, 2);
            s1 += __shfl_xor_sync(0xffffffffu, s1, 1);
            s1 += __shfl_xor_sync(0xffffffffu, s1, 2);
            const float n0 = rsqrtf(s0 * (1.0f / 64.0f) + 0.01f) * outScale;
            const float n1 = rsqrtf(s1 * (1.0f / 64.0f) + 0.01f) * outScale;
            const int r0 = warp_m + mt * 16 + g;
#pragma unroll
            for (int nt = 0; nt < 8; nt++) {
                const int c = warp_n + nt * 8 + tig * 2;
                *(float2*)(Cg + (size_t)r0 * ldc + c) =
                    make_float2(acc[mt][nt][0] * n0 * w[nt * 2], acc[mt][nt][1] * n0 * w[nt * 2 + 1]);
                *(float2*)(Cg + (size_t)(r0 + 8) * ldc + c) =
                    make_float2(acc[mt][nt][2] * n1 * w[nt * 2], acc[mt][nt][3] * n1 * w[nt * 2 + 1]);
            }
        }
    }
}

// ---------------------------------------------------------------------------
// Fused QKV projection + per-head RMSNorm epilogue: grid (12, 32).
// nb 0..7 -> q (norm, *1/8), 8..9 -> k (norm), 10..11 -> v (plain).
// Reads pre-rounded g_xr / g_w*r.
// ---------------------------------------------------------------------------
__global__ void __launch_bounds__(256, 2)
qkv_kernel(const float* __restrict__ qnw, const float* __restrict__ knw)
{
    const int nb = blockIdx.x;
    const int mb = blockIdx.y;
    const float* Bg;
    float* Cg;
    int ldc;
    const float* nw;
    float sc;
    if (nb < 8) {
        Bg  = g_wqr + (size_t)nb * 128 * DIMK;
        Cg  = g_q + (size_t)mb * 128 * 1024 + nb * 128;
        ldc = 1024; nw = qnw; sc = 0.125f;     // fold softmax 1/sqrt(64)
    } else if (nb < 10) {
        int t = nb - 8;
        Bg  = g_wkr + (size_t)t * 128 * DIMK;
        Cg  = g_k + (size_t)mb * 128 * 256 + t * 128;
        ldc = 256; nw = knw; sc = 1.0f;
    } else {
        int t = nb - 10;
        Bg  = g_wvr + (size_t)t * 128 * DIMK;
        Cg  = g_v + (size_t)mb * 128 * 256 + t * 128;
        ldc = 256; nw = nullptr; sc = 1.0f;
    }
    gemm128_tc(g_xr + (size_t)mb * 128 * DIMK, Bg, Cg, ldc, nw, sc);
}

// ---------------------------------------------------------------------------
// Output projection: out = g_ao @ wo^T, grid (8, 32). Reads pre-rounded data.
// ---------------------------------------------------------------------------
__global__ void __launch_bounds__(256, 2)
oproj_kernel(float* __restrict__ out)
{
    gemm128_tc(g_ao  + (size_t)blockIdx.y * 128 * 1024,
               g_wor + (size_t)blockIdx.x * 128 * DIMK,
               out   + (size_t)blockIdx.y * 128 * 1024 + blockIdx.x * 128,
               1024, nullptr, 1.0f);
}

// ---------------------------------------------------------------------------
// Sliding-window ALiBi attention (R12 layout, passing). Output stores are
// tf32-rounded so oproj can cp.async raw.
// ---------------------------------------------------------------------------
__global__ void attn_kernel()
{
    const int gw   = (blockIdx.x * blockDim.x + threadIdx.x) >> 5;
    const int lane = threadIdx.x & 31;
    const int gid  = lane >> 3;
    const int sub  = lane & 7;
    const int b   = gw >> 13;
    const int h   = (gw >> 9) & 15;
    const int i0  = (gw & 511) << 2;
    const int i   = i0 + gid;
    const int kvh = h & 3;

    const float slope = exp2f(-0.5f * (float)(h + 1));

    const float* qp = g_q + ((size_t)(b * LSEQ + i) * 1024) + h * 64 + sub * 8;
    const float4 q0 = *(const float4*)qp;
    const float4 q1 = *(const float4*)(qp + 4);

    const float* kp = g_k + (size_t)b * LSEQ * 256 + kvh * 64 + sub * 8;
    const float* vp = g_v + (size_t)b * LSEQ * 256 + kvh * 64 + sub * 8;

    float m = -1e30f, l = 0.0f;
    float o0 = 0.f, o1 = 0.f, o2 = 0.f, o3 = 0.f;
    float o4 = 0.f, o5 = 0.f, o6 = 0.f, o7 = 0.f;

    int jlo = i0 - 16; if (jlo < 0) jlo = 0;
    for (int j = jlo; j <= i0 + 3; j++) {
        const float* kr = kp + (size_t)j * 256;
        const float* vr = vp + (size_t)j * 256;
        const float4 k0 = *(const float4*)kr;
        const float4 k1 = *(const float4*)(kr + 4);
        const float4 v0 = *(const float4*)vr;
        const float4 v1 = *(const float4*)(vr + 4);

        float s = q0.x * k0.x + q0.y * k0.y + q0.z * k0.z + q0.w * k0.w
                + q1.x * k1.x + q1.y * k1.y + q1.z * k1.z + q1.w * k1.w;
        s += __shfl_xor_sync(0xffffffffu, s, 1);
        s += __shfl_xor_sync(0xffffffffu, s, 2);
        s += __shfl_xor_sync(0xffffffffu, s, 4);

        const bool active = (j <= i) && (j >= i - 16);
        if (active) {
            s += slope * (float)(j - i);
            const float mn = fmaxf(m, s);
            const float c  = __expf(m - mn);
            const float p  = __expf(s - mn);
            l  = l * c + p;
            o0 = o0 * c + p * v0.x;  o1 = o1 * c + p * v0.y;
            o2 = o2 * c + p * v0.z;  o3 = o3 * c + p * v0.w;
            o4 = o4 * c + p * v1.x;  o5 = o5 * c + p * v1.y;
            o6 = o6 * c + p * v1.z;  o7 = o7 * c + p * v1.w;
            m = mn;
        }
    }

    const float inv = 1.0f / l;
    float* op = g_ao + ((size_t)(b * LSEQ + i) * 1024) + h * 64 + sub * 8;
    uint4 w0, w1;
    w0.x = f2tf(o0 * inv); w0.y = f2tf(o1 * inv); w0.z = f2tf(o2 * inv); w0.w = f2tf(o3 * inv);
    w1.x = f2tf(o4 * inv); w1.y = f2tf(o5 * inv); w1.z = f2tf(o6 * inv); w1.w = f2tf(o7 * inv);
    *(uint4*)op       = w0;
    *(uint4*)(op + 4) = w1;
}

// ---------------------------------------------------------------------------
// Launch sequence (graph-capturable: kernel launches only, default stream)
// Inputs: 0=x, 1=wq, 2=wk, 3=wv, 4=wo, 5=q_norm_w, 6=k_norm_w
// ---------------------------------------------------------------------------
extern "C" void kernel_launch(void* const* d_in, const int* in_sizes, int n_in,
                              void* d_out, int out_size)
{
    const float* x   = (const float*)d_in[0];
    const float* wq  = (const float*)d_in[1];
    const float* wk  = (const float*)d_in[2];
    const float* wv  = (const float*)d_in[3];
    const float* wo  = (const float*)d_in[4];
    const float* qnw = (const float*)d_in[5];
    const float* knw = (const float*)d_in[6];
    float* out = (float*)d_out;

    cudaFuncSetAttribute((const void*)qkv_kernel,
                         cudaFuncAttributeMaxDynamicSharedMemorySize, DSMEM_SZ);
    cudaFuncSetAttribute((const void*)oproj_kernel,
                         cudaFuncAttributeMaxDynamicSharedMemorySize, DSMEM_SZ);

    // 0) Pre-round operands to tf32 (x, wq, wk, wv, wo)
    round_kernel<<<1664, 256>>>(x, wq, wk, wv, wo);

    // 1) QKV projection + fused RMSNorm epilogue (tensor cores, cp.async ring)
    qkv_kernel<<<dim3(12, 32), 256, DSMEM_SZ>>>(qnw, knw);

    // 2) Sliding-window ALiBi attention (rounds its output to tf32)
    attn_kernel<<<2048, 256>>>();

    // 3) Output projection (tensor cores, cp.async ring)
    oproj_kernel<<<dim3(8, 32), 256, DSMEM_SZ>>>(out);
}

// round 16
// speedup vs baseline: 1.8319x; 1.8319x over previous
#include <cuda_runtime.h>
#include <cuda_fp16.h>
#include <math.h>
#include <stdint.h>

// Problem constants
#define TOK   4096   // B*L = 2*2048
#define DIMK  1024
#define HQ    16
#define HKV   4
#define HD    64
#define LSEQ  2048

// Scratch (static device globals — allocation-free)
__device__ float  g_q  [TOK * HQ  * HD];  // fp32 (normed * 1/8) for attention
__device__ float  g_k  [TOK * HKV * HD];  // fp32 (normed)
__device__ float  g_v  [TOK * HKV * HD];  // fp32
__device__ __half g_aoh[TOK * HQ * HD];   // attention out (fp16, oproj A operand)

// fp16 operands for the GEMMs
__device__ __half g_xh [TOK * DIMK];
__device__ __half g_wqh[HQ  * HD * DIMK];
__device__ __half g_wkh[HKV * HD * DIMK];
__device__ __half g_wvh[HKV * HD * DIMK];
__device__ __half g_woh[DIMK * HQ * HD];

// ---------------------------------------------------------------------------
// helpers
// ---------------------------------------------------------------------------
__device__ __forceinline__ uint32_t smem_u32(const void* p) {
    uint32_t a;
    asm("{ .reg .u64 t; cvta.to.shared.u64 t, %1; cvt.u32.u64 %0, t; }" : "=r"(a) : "l"(p));
    return a;
}

__device__ __forceinline__ void cp16(uint32_t dst, const void* src) {
    asm volatile("cp.async.cg.shared.global [%0], [%1], 16;" :: "r"(dst), "l"(src));
}
__device__ __forceinline__ void cp_commit() {
    asm volatile("cp.async.commit_group;" ::: "memory");
}
template <int N>
__device__ __forceinline__ void cp_wait() {
    asm volatile("cp.async.wait_group %0;" :: "n"(N) : "memory");
}

__device__ __forceinline__ void ldm_x4(unsigned& r0, unsigned& r1, unsigned& r2, unsigned& r3,
                                       uint32_t addr) {
    asm volatile("ldmatrix.sync.aligned.m8n8.x4.shared.b16 {%0,%1,%2,%3}, [%4];"
                 : "=r"(r0), "=r"(r1), "=r"(r2), "=r"(r3) : "r"(addr));
}

__device__ __forceinline__ void mma_f16(float& c0, float& c1, float& c2, float& c3,
                                        unsigned a0, unsigned a1, unsigned a2, unsigned a3,
                                        unsigned b0, unsigned b1)
{
    asm volatile(
        "mma.sync.aligned.m16n8k16.row.col.f32.f16.f16.f32 "
        "{%0,%1,%2,%3}, {%4,%5,%6,%7}, {%8,%9}, {%0,%1,%2,%3};"
        : "+f"(c0), "+f"(c1), "+f"(c2), "+f"(c3)
        : "r"(a0), "r"(a1), "r"(a2), "r"(a3), "r"(b0), "r"(b1));
}

__device__ __forceinline__ unsigned h2bits(float a, float b) {
    __half2 h = __floats2half2_rn(a, b);
    return *reinterpret_cast<unsigned*>(&h);
}

// ---------------------------------------------------------------------------
// Conversion prepass: fp32 -> fp16. Blocks: x 2048, wq 512, wk 128, wv 128,
// wo 512 (total 3328); each block 2048 elems (256 thr x 8).
// ---------------------------------------------------------------------------
__global__ void conv_kernel(const float* __restrict__ x,  const float* __restrict__ wq,
                            const float* __restrict__ wk, const float* __restrict__ wv,
                            const float* __restrict__ wo)
{
    const int b = blockIdx.x;
    const float* src;
    __half* dst;
    int base;
    if      (b < 2048) { src = x;  dst = g_xh;  base = b; }
    else if (b < 2560) { src = wq; dst = g_wqh; base = b - 2048; }
    else if (b < 2688) { src = wk; dst = g_wkh; base = b - 2560; }
    else if (b < 2816) { src = wv; dst = g_wvh; base = b - 2688; }
    else               { src = wo; dst = g_woh; base = b - 2816; }
    const size_t off = (size_t)base * 2048 + threadIdx.x * 8;
    float4 v0 = *(const float4*)(src + off);
    float4 v1 = *(const float4*)(src + off + 4);
    uint4 o;
    o.x = h2bits(v0.x, v0.y);
    o.y = h2bits(v0.z, v0.w);
    o.z = h2bits(v1.x, v1.y);
    o.w = h2bits(v1.z, v1.w);
    *(uint4*)(dst + off) = o;
}

// ---------------------------------------------------------------------------
// 128x128 tile fp16 GEMM, C[m,n] = sum_k A[m,k]*B[n,k] (both [rows][k],
// k contiguous, stride DIMK). BK=64 halves, 3-stage cp.async ring.
// 256 threads, 8 warps (4x2), warp tile 32x64 via m16n8k16 + ldmatrix.
// Smem row = 128B = 8 chunks of 16B; swizzle: phys_chunk = chunk ^ (row&7).
// Optional fused per-head RMSNorm epilogue (64-col warp span = one head).
// ---------------------------------------------------------------------------
#define STG_B       16384              // one operand, one stage (128 x 128B)
#define STAGE_BYTES 32768              // A+B
#define NSTAGE 3
#define DSMEM_SZ (NSTAGE * STAGE_BYTES)  // 98304
#define NSLAB (DIMK / 64)              // 16

__device__ __forceinline__ void gemm128_fp16(const __half* __restrict__ Ag,
                                             const __half* __restrict__ Bg,
                                             float*        __restrict__ Cg,
                                             int ldc,
                                             const float* __restrict__ nw,
                                             float outScale)
{
    extern __shared__ char shraw[];
    const uint32_t sbase = smem_u32(shraw);

    const int tid    = threadIdx.x;
    const int lane   = tid & 31;
    const int wid    = tid >> 5;
    const int warp_m = (wid & 3) * 32;
    const int warp_n = (wid >> 2) * 64;
    const int g      = lane >> 2;
    const int tig    = lane & 3;

    float acc[2][8][4];
#pragma unroll
    for (int mt = 0; mt < 2; mt++)
#pragma unroll
        for (int nt = 0; nt < 8; nt++)
#pragma unroll
            for (int c = 0; c < 4; c++) acc[mt][nt][c] = 0.0f;

    // ---- staging (cp.async): thread -> row = tid>>1, 4 chunks of 16B each op
    const int srow = tid >> 1;
    const int hsel = tid & 1;                    // chunk group 0..3 / 4..7
    const __half* Ap = Ag + (size_t)srow * DIMK + hsel * 32;
    const __half* Bp = Bg + (size_t)srow * DIMK + hsel * 32;
    uint32_t dstoff[4];
#pragma unroll
    for (int i = 0; i < 4; i++) {
        const int ch = hsel * 4 + i;
        dstoff[i] = srow * 128 + ((ch ^ (srow & 7)) << 4);
    }

#define ISSUE_SLAB(s)                                                       \
    do {                                                                    \
        const uint32_t stb = sbase + ((s) % NSTAGE) * STAGE_BYTES;          \
        const __half* a_ = Ap + (s) * 64;                                   \
        const __half* b_ = Bp + (s) * 64;                                   \
        _Pragma("unroll")                                                   \
        for (int i_ = 0; i_ < 4; i_++) {                                    \
            cp16(stb + dstoff[i_],         a_ + i_ * 8);                    \
            cp16(stb + STG_B + dstoff[i_], b_ + i_ * 8);                    \
        }                                                                   \
        cp_commit();                                                        \
    } while (0)

    // ---- fragment addressing (ldmatrix) -----------------------------------
    // A (per mt): lanes 0..15 -> rows, lanes 16..31 -> same rows, k+8 chunk
    uint32_t rowA[2];
    int r7A[2];
#pragma unroll
    for (int mt = 0; mt < 2; mt++) {
        const int r = warp_m + mt * 16 + (lane & 15);
        rowA[mt] = r * 128;
        r7A[mt]  = r & 7;
    }
    const int cgA = lane >> 4;   // k-chunk offset 0/1

    // B (per ntp): 4 groups of 8 lanes: (n0-7,k0),(n8-15,k0),(n0-7,k8),(n8-15,k8)
    uint32_t rowB[4];
    int r7B[4];
#pragma unroll
    for (int ntp = 0; ntp < 4; ntp++) {
        const int r = warp_n + ntp * 16 + ((lane >> 3) & 1) * 8 + (lane & 7);
        rowB[ntp] = r * 128;
        r7B[ntp]  = r & 7;
    }
    const int cgB = lane >> 4;

    ISSUE_SLAB(0);
    ISSUE_SLAB(1);

    for (int s = 0; s < NSLAB; s++) {
        cp_wait<1>();
        __syncthreads();

        if (s + 2 < NSLAB) ISSUE_SLAB(s + 2);

        const uint32_t stA = sbase + (s % NSTAGE) * STAGE_BYTES;
        const uint32_t stB = stA + STG_B;

#pragma unroll
        for (int ks = 0; ks < 4; ks++) {
            const int kc = 2 * ks;    // base 16B chunk of this k16 step
            unsigned a[2][4];
#pragma unroll
            for (int mt = 0; mt < 2; mt++) {
                const uint32_t ad = stA + rowA[mt] + (((kc + cgA) ^ r7A[mt]) << 4);
                ldm_x4(a[mt][0], a[mt][1], a[mt][2], a[mt][3], ad);
            }
#pragma unroll
            for (int ntp = 0; ntp < 4; ntp++) {
                unsigned b0, b1, b2, b3;
                const uint32_t bd = stB + rowB[ntp] + (((kc + cgB) ^ r7B[ntp]) << 4);
                ldm_x4(b0, b1, b2, b3, bd);
                const int n0 = 2 * ntp, n1 = 2 * ntp + 1;
                mma_f16(acc[0][n0][0], acc[0][n0][1], acc[0][n0][2], acc[0][n0][3],
                        a[0][0], a[0][1], a[0][2], a[0][3], b0, b2);
                mma_f16(acc[1][n0][0], acc[1][n0][1], acc[1][n0][2], acc[1][n0][3],
                        a[1][0], a[1][1], a[1][2], a[1][3], b0, b2);
                mma_f16(acc[0][n1][0], acc[0][n1][1], acc[0][n1][2], acc[0][n1][3],
                        a[0][0], a[0][1], a[0][2], a[0][3], b1, b3);
                mma_f16(acc[1][n1][0], acc[1][n1][1], acc[1][n1][2], acc[1][n1][3],
                        a[1][0], a[1][1], a[1][2], a[1][3], b1, b3);
            }
        }
        __syncthreads();
    }
#undef ISSUE_SLAB

    // ---------------- Epilogue ----------------
    if (nw == nullptr) {
#pragma unroll
        for (int mt = 0; mt < 2; mt++)
#pragma unroll
            for (int nt = 0; nt < 8; nt++) {
                const int r0 = warp_m + mt * 16 + g;
                const int c  = warp_n + nt * 8 + tig * 2;
                *(float2*)(Cg + (size_t)r0 * ldc + c)       = make_float2(acc[mt][nt][0], acc[mt][nt][1]);
                *(float2*)(Cg + (size_t)(r0 + 8) * ldc + c) = make_float2(acc[mt][nt][2], acc[mt][nt][3]);
            }
    } else {
        // Fused per-head RMSNorm: warp's 64-col span is one 64-dim head.
        float w[16];
#pragma unroll
        for (int nt = 0; nt < 8; nt++) {
            float2 ww = *(const float2*)(nw + nt * 8 + tig * 2);
            w[nt * 2]     = ww.x;
            w[nt * 2 + 1] = ww.y;
        }
#pragma unroll
        for (int mt = 0; mt < 2; mt++) {
            float s0 = 0.f, s1 = 0.f;
#pragma unroll
            for (int nt = 0; nt < 8; nt++) {
                s0 += acc[mt][nt][0] * acc[mt][nt][0] + acc[mt][nt][1] * acc[mt][nt][1];
                s1 += acc[mt][nt][2] * acc[mt][nt][2] + acc[mt][nt][3] * acc[mt][nt][3];
            }
            s0 += __shfl_xor_sync(0xffffffffu, s0, 1);
            s0 += __shfl_xor_sync(0xffffffffu, s0, 2);
            s1 += __shfl_xor_sync(0xffffffffu, s1, 1);
            s1 += __shfl_xor_sync(0xffffffffu, s1, 2);
            const float n0 = rsqrtf(s0 * (1.0f / 64.0f) + 0.01f) * outScale;
            const float n1 = rsqrtf(s1 * (1.0f / 64.0f) + 0.01f) * outScale;
            const int r0 = warp_m + mt * 16 + g;
#pragma unroll
            for (int nt = 0; nt < 8; nt++) {
                const int c = warp_n + nt * 8 + tig * 2;
                *(float2*)(Cg + (size_t)r0 * ldc + c) =
                    make_float2(acc[mt][nt][0] * n0 * w[nt * 2], acc[mt][nt][1] * n0 * w[nt * 2 + 1]);
                *(float2*)(Cg + (size_t)(r0 + 8) * ldc + c) =
                    make_float2(acc[mt][nt][2] * n1 * w[nt * 2], acc[mt][nt][3] * n1 * w[nt * 2 + 1]);
            }
        }
    }
}

// ---------------------------------------------------------------------------
// Fused QKV projection + per-head RMSNorm epilogue: grid (12, 32).
// nb 0..7 -> q (norm, *1/8), 8..9 -> k (norm), 10..11 -> v (plain).
// ---------------------------------------------------------------------------
__global__ void __launch_bounds__(256, 2)
qkv_kernel(const float* __restrict__ qnw, const float* __restrict__ knw)
{
    const int nb = blockIdx.x;
    const int mb = blockIdx.y;
    const __half* Bg;
    float* Cg;
    int ldc;
    const float* nw;
    float sc;
    if (nb < 8) {
        Bg  = g_wqh + (size_t)nb * 128 * DIMK;
        Cg  = g_q + (size_t)mb * 128 * 1024 + nb * 128;
        ldc = 1024; nw = qnw; sc = 0.125f;     // fold softmax 1/sqrt(64)
    } else if (nb < 10) {
        int t = nb - 8;
        Bg  = g_wkh + (size_t)t * 128 * DIMK;
        Cg  = g_k + (size_t)mb * 128 * 256 + t * 128;
        ldc = 256; nw = knw; sc = 1.0f;
    } else {
        int t = nb - 10;
        Bg  = g_wvh + (size_t)t * 128 * DIMK;
        Cg  = g_v + (size_t)mb * 128 * 256 + t * 128;
        ldc = 256; nw = nullptr; sc = 1.0f;
    }
    gemm128_fp16(g_xh + (size_t)mb * 128 * DIMK, Bg, Cg, ldc, nw, sc);
}

// ---------------------------------------------------------------------------
// Output projection: out = g_aoh @ wo^T, grid (8, 32).
// ---------------------------------------------------------------------------
__global__ void __launch_bounds__(256, 2)
oproj_kernel(float* __restrict__ out)
{
    gemm128_fp16(g_aoh + (size_t)blockIdx.y * 128 * 1024,
                 g_woh + (size_t)blockIdx.x * 128 * DIMK,
                 out   + (size_t)blockIdx.y * 128 * 1024 + blockIdx.x * 128,
                 1024, nullptr, 1.0f);
}

// ---------------------------------------------------------------------------
// Sliding-window ALiBi attention (R12 layout). fp32 math; stores fp16 output.
// Warp = 4 queries of one (b,h) as four 8-lane groups; lane owns 8 dims.
// ---------------------------------------------------------------------------
__global__ void attn_kernel()
{
    const int gw   = (blockIdx.x * blockDim.x + threadIdx.x) >> 5;
    const int lane = threadIdx.x & 31;
    const int gid  = lane >> 3;
    const int sub  = lane & 7;
    const int b   = gw >> 13;
    const int h   = (gw >> 9) & 15;
    const int i0  = (gw & 511) << 2;
    const int i   = i0 + gid;
    const int kvh = h & 3;

    const float slope = exp2f(-0.5f * (float)(h + 1));

    const float* qp = g_q + ((size_t)(b * LSEQ + i) * 1024) + h * 64 + sub * 8;
    const float4 q0 = *(const float4*)qp;
    const float4 q1 = *(const float4*)(qp + 4);

    const float* kp = g_k + (size_t)b * LSEQ * 256 + kvh * 64 + sub * 8;
    const float* vp = g_v + (size_t)b * LSEQ * 256 + kvh * 64 + sub * 8;

    float m = -1e30f, l = 0.0f;
    float o0 = 0.f, o1 = 0.f, o2 = 0.f, o3 = 0.f;
    float o4 = 0.f, o5 = 0.f, o6 = 0.f, o7 = 0.f;

    int jlo = i0 - 16; if (jlo < 0) jlo = 0;
    for (int j = jlo; j <= i0 + 3; j++) {
        const float* kr = kp + (size_t)j * 256;
        const float* vr = vp + (size_t)j * 256;
        const float4 k0 = *(const float4*)kr;
        const float4 k1 = *(const float4*)(kr + 4);
        const float4 v0 = *(const float4*)vr;
        const float4 v1 = *(const float4*)(vr + 4);

        float s = q0.x * k0.x + q0.y * k0.y + q0.z * k0.z + q0.w * k0.w
                + q1.x * k1.x + q1.y * k1.y + q1.z * k1.z + q1.w * k1.w;
        s += __shfl_xor_sync(0xffffffffu, s, 1);
        s += __shfl_xor_sync(0xffffffffu, s, 2);
        s += __shfl_xor_sync(0xffffffffu, s, 4);

        const bool active = (j <= i) && (j >= i - 16);
        if (active) {
            s += slope * (float)(j - i);
            const float mn = fmaxf(m, s);
            const float c  = __expf(m - mn);
            const float p  = __expf(s - mn);
            l  = l * c + p;
            o0 = o0 * c + p * v0.x;  o1 = o1 * c + p * v0.y;
            o2 = o2 * c + p * v0.z;  o3 = o3 * c + p * v0.w;
            o4 = o4 * c + p * v1.x;  o5 = o5 * c + p * v1.y;
            o6 = o6 * c + p * v1.z;  o7 = o7 * c + p * v1.w;
            m = mn;
        }
    }

    const float inv = 1.0f / l;
    __half* op = g_aoh + ((size_t)(b * LSEQ + i) * 1024) + h * 64 + sub * 8;
    uint4 o;
    o.x = h2bits(o0 * inv, o1 * inv);
    o.y = h2bits(o2 * inv, o3 * inv);
    o.z = h2bits(o4 * inv, o5 * inv);
    o.w = h2bits(o6 * inv, o7 * inv);
    *(uint4*)op = o;
}

// ---------------------------------------------------------------------------
// Launch sequence (graph-capturable: kernel launches only, default stream)
// Inputs: 0=x, 1=wq, 2=wk, 3=wv, 4=wo, 5=q_norm_w, 6=k_norm_w
// ---------------------------------------------------------------------------
extern "C" void kernel_launch(void* const* d_in, const int* in_sizes, int n_in,
                              void* d_out, int out_size)
{
    const float* x   = (const float*)d_in[0];
    const float* wq  = (const float*)d_in[1];
    const float* wk  = (const float*)d_in[2];
    const float* wv  = (const float*)d_in[3];
    const float* wo  = (const float*)d_in[4];
    const float* qnw = (const float*)d_in[5];
    const float* knw = (const float*)d_in[6];
    float* out = (float*)d_out;

    cudaFuncSetAttribute((const void*)qkv_kernel,
                         cudaFuncAttributeMaxDynamicSharedMemorySize, DSMEM_SZ);
    cudaFuncSetAttribute((const void*)oproj_kernel,
                         cudaFuncAttributeMaxDynamicSharedMemorySize, DSMEM_SZ);

    // 0) Convert operands to fp16
    conv_kernel<<<3328, 256>>>(x, wq, wk, wv, wo);

    // 1) QKV projection + fused RMSNorm epilogue (fp16 tensor cores)
    qkv_kernel<<<dim3(12, 32), 256, DSMEM_SZ>>>(qnw, knw);

    // 2) Sliding-window ALiBi attention (writes fp16 output)
    attn_kernel<<<2048, 256>>>();

    // 3) Output projection (fp16 tensor cores)
    oproj_kernel<<<dim3(8, 32), 256, DSMEM_SZ>>>(out);
}